// round 16
// baseline (speedup 1.0000x reference)
#include <cuda_runtime.h>
#include <cuda_bf16.h>

// Problem constants
#define BATCH 8
#define CIN   128
#define COUT  128
#define HH    128
#define WW    128

#define CI_CHUNK 8
#define XS_PITCH 132                  // 128 + halo(2) + pad, floats
#define XS_FLOATS (CI_CHUNK * 3 * XS_PITCH)      // 3168
#define WS_FLOATS (CI_CHUNK * 9 * COUT)          // 9216
#define SMEM_BYTES ((XS_FLOATS + WS_FLOATS) * 4) // 49536

// Pre-transposed weights: wT[(ci*9 + k)*128 + co] = W[co][ci][kh][kw], k = kh*3+kw
__device__ float g_wT[CIN * 9 * COUT];

__global__ void transpose_w_kernel(const float* __restrict__ w)
{
    int i = blockIdx.x * blockDim.x + threadIdx.x;
    if (i < CIN * 9 * COUT) {
        int co = i % COUT;
        int k  = (i / COUT) % 9;
        int ci = i / (COUT * 9);
        g_wT[i] = w[(co * CIN + ci) * 9 + k];
    }
}

extern __shared__ float smem_dyn[];

__global__ __launch_bounds__(256)
void conv_masked_kernel(const float* __restrict__ x,
                        const int*   __restrict__ mask,
                        const float* __restrict__ bias,
                        float*       __restrict__ out)
{
    const int h   = blockIdx.x;   // output row
    const int b   = blockIdx.y;   // batch
    const int tid = threadIdx.x;

    float* xs = smem_dyn;               // [CI_CHUNK][3][XS_PITCH]
    float* ws = smem_dyn + XS_FLOATS;   // [CI_CHUNK][9][COUT]

    __shared__ float act[WW];
    __shared__ int   mrow[WW + 2];

    // ---- active-site mask for this (b, h) row: 3x3 window OR of mask!=0 ----
    if (tid < WW) {
        int m = 0;
        #pragma unroll
        for (int r = 0; r < 3; r++) {
            int hh = h - 1 + r;
            if ((unsigned)hh < HH)
                m |= (mask[(b * HH + hh) * WW + tid] != 0);
        }
        mrow[tid + 1] = m;
    }
    if (tid == 0) { mrow[0] = 0; mrow[WW + 1] = 0; }
    __syncthreads();
    if (tid < WW)
        act[tid] = (mrow[tid] | mrow[tid + 1] | mrow[tid + 2]) ? 1.0f : 0.0f;
    // visibility of act[] to all threads is guaranteed by the __syncthreads()
    // at the top of the first main-loop iteration below.

    const int ct  = tid >> 4;   // 0..15 (c_out group)
    const int wt  = tid & 15;   // 0..15 (w group)
    const int co0 = ct * 8;
    const int w0  = wt * 8;

    float acc[8][8];
    #pragma unroll
    for (int i = 0; i < 8; i++)
        #pragma unroll
        for (int j = 0; j < 8; j++)
            acc[i][j] = 0.0f;

    // ---- main loop over input-channel chunks ----
    for (int cc = 0; cc < CIN / CI_CHUNK; cc++) {
        __syncthreads();   // protect previous iteration's smem reads

        // weights: coalesced from pre-transposed g_wT
        #pragma unroll 4
        for (int i = tid; i < WS_FLOATS; i += 256)
            ws[i] = g_wT[cc * WS_FLOATS + i];

        // x tile with halo (rows h-1..h+1, cols -1..130), zero padded
        #pragma unroll 4
        for (int i = tid; i < XS_FLOATS; i += 256) {
            int ci  = i / (3 * XS_PITCH);
            int rem = i - ci * 3 * XS_PITCH;
            int r   = rem / XS_PITCH;
            int wi  = rem - r * XS_PITCH;
            int w   = wi - 1;
            int hh  = h - 1 + r;
            float v = 0.0f;
            if ((unsigned)w < WW && (unsigned)hh < HH)
                v = x[((b * CIN + cc * CI_CHUNK + ci) * HH + hh) * WW + w];
            xs[i] = v;
        }
        __syncthreads();

        #pragma unroll 1
        for (int ci = 0; ci < CI_CHUNK; ci++) {
            #pragma unroll
            for (int r = 0; r < 3; r++) {
                const float* xrow = &xs[(ci * 3 + r) * XS_PITCH + w0];
                float xv[10];
                #pragma unroll
                for (int u = 0; u < 10; u++) xv[u] = xrow[u];

                #pragma unroll
                for (int kw = 0; kw < 3; kw++) {
                    const float4* wr = reinterpret_cast<const float4*>(
                        &ws[(ci * 9 + r * 3 + kw) * COUT + co0]);
                    float4 wa = wr[0];
                    float4 wb = wr[1];
                    float wv[8] = { wa.x, wa.y, wa.z, wa.w,
                                    wb.x, wb.y, wb.z, wb.w };
                    #pragma unroll
                    for (int i = 0; i < 8; i++)
                        #pragma unroll
                        for (int j = 0; j < 8; j++)
                            acc[i][j] = fmaf(wv[i], xv[j + kw], acc[i][j]);
                }
            }
        }
    }

    // ---- epilogue: (+bias) * active, float4 stores ----
    float av[8];
    #pragma unroll
    for (int j = 0; j < 8; j++) av[j] = act[w0 + j];

    #pragma unroll
    for (int i = 0; i < 8; i++) {
        float bv = __ldg(&bias[co0 + i]);
        float4 o0, o1;
        o0.x = (acc[i][0] + bv) * av[0];
        o0.y = (acc[i][1] + bv) * av[1];
        o0.z = (acc[i][2] + bv) * av[2];
        o0.w = (acc[i][3] + bv) * av[3];
        o1.x = (acc[i][4] + bv) * av[4];
        o1.y = (acc[i][5] + bv) * av[5];
        o1.z = (acc[i][6] + bv) * av[6];
        o1.w = (acc[i][7] + bv) * av[7];
        float4* op = reinterpret_cast<float4*>(
            &out[((b * COUT + co0 + i) * HH + h) * WW + w0]);
        op[0] = o0;
        op[1] = o1;
    }
}

extern "C" void kernel_launch(void* const* d_in, const int* in_sizes, int n_in,
                              void* d_out, int out_size)
{
    const float* x    = (const float*)d_in[0];   // [8,128,128,128] f32
    const int*   mask = (const int*)  d_in[1];   // [8,1,128,128] i32
    const float* w    = (const float*)d_in[2];   // [128,128,3,3] f32
    const float* bias = (const float*)d_in[3];   // [128] f32
    float*       out  = (float*)d_out;           // [8,128,128,128] f32

    (void)in_sizes; (void)n_in; (void)out_size;

    // opt-in for >48KB dynamic smem (host attribute call, capture-safe,
    // idempotent — called every time, no static guards)
    cudaFuncSetAttribute(conv_masked_kernel,
                         cudaFuncAttributeMaxDynamicSharedMemorySize,
                         SMEM_BYTES);

    // 1) one-shot weight transpose into __device__ scratch (coalesced reloads)
    int wtotal = CIN * 9 * COUT;
    transpose_w_kernel<<<(wtotal + 255) / 256, 256>>>(w);

    // 2) main masked conv
    dim3 grid(HH, BATCH);   // one CTA per (h, b) output row
    conv_masked_kernel<<<grid, 256, SMEM_BYTES>>>(x, mask, bias, out);
}